// round 3
// baseline (speedup 1.0000x reference)
#include <cuda_runtime.h>
#include <cuda_bf16.h>

#define NN 50000
#define EE 800000
#define HH 4
#define DD 64

// ---------------- scratch (device globals; allocation-free) ----------------
__device__ float  g_z [NN * HH * DD];     // 51.2 MB  z buffer (also reused for layer-3 [N,8])
__device__ float  g_el[NN * HH];
__device__ float  g_er[NN * HH];
__device__ float  g_a [(EE + NN) * HH];   // per-edge exp(e)
__device__ float  g_s [NN * HH];          // softmax denominators
__device__ float  g_h [NN * DD];          // layer activations (ping-pong not needed)
__device__ double g_bnsum[DD], g_bnsq[DD];
__device__ float  g_scale[DD], g_shift[DD];

// ---------------- GEMM (M=256) + fused el/er ----------------
// block = 256 threads, 8 rows/block; thread t: cols 4*(t&63).. , rows (t>>6)*2 + {0,1}
template<int KIN>
__global__ void gemm256_attn(const float* __restrict__ x, const float* __restrict__ W,
                             const float* __restrict__ al, const float* __restrict__ ar,
                             float* __restrict__ z, float* __restrict__ el,
                             float* __restrict__ er, int n)
{
    __shared__ float xs[8][KIN];
    __shared__ float el_s[8][4], er_s[8][4];
    int t = threadIdx.x;
    int base = blockIdx.x * 8;
    for (int idx = t; idx < 8 * KIN; idx += 256) {
        int r = idx / KIN, k = idx - r * KIN;
        int row = base + r;
        xs[r][k] = (row < n) ? x[row * KIN + k] : 0.f;
    }
    __syncthreads();
    int c4 = t & 63, rr = t >> 6;
    const float4* W4 = (const float4*)W;
    float acc[2][4] = {};
    #pragma unroll
    for (int k = 0; k < KIN; k++) {
        float4 w = W4[k * 64 + c4];
        #pragma unroll
        for (int r2 = 0; r2 < 2; r2++) {
            float xv = xs[rr * 2 + r2][k];
            acc[r2][0] += xv * w.x; acc[r2][1] += xv * w.y;
            acc[r2][2] += xv * w.z; acc[r2][3] += xv * w.w;
        }
    }
    float4 alv = ((const float4*)al)[c4];
    float4 arv = ((const float4*)ar)[c4];
    #pragma unroll
    for (int r2 = 0; r2 < 2; r2++) {
        int row = base + rr * 2 + r2;
        if (row < n)
            ((float4*)z)[(size_t)row * 64 + c4] =
                make_float4(acc[r2][0], acc[r2][1], acc[r2][2], acc[r2][3]);
        float p = acc[r2][0]*alv.x + acc[r2][1]*alv.y + acc[r2][2]*alv.z + acc[r2][3]*alv.w;
        float q = acc[r2][0]*arv.x + acc[r2][1]*arv.y + acc[r2][2]*arv.z + acc[r2][3]*arv.w;
        #pragma unroll
        for (int off = 8; off; off >>= 1) {
            p += __shfl_xor_sync(0xffffffffu, p, off);
            q += __shfl_xor_sync(0xffffffffu, q, off);
        }
        if ((t & 15) == 0) {   // one writer per 16-lane (head) group
            el_s[rr * 2 + r2][c4 >> 4] = p;
            er_s[rr * 2 + r2][c4 >> 4] = q;
        }
    }
    __syncthreads();
    if (t < 32) {
        int r = t >> 2, hh = t & 3;
        int row = base + r;
        if (row < n) { el[row * 4 + hh] = el_s[r][hh]; er[row * 4 + hh] = er_s[r][hh]; }
    }
}

// ---------------- GEMM (M=8, layer 3) + fused el/er ----------------
__global__ void gemm8_attn(const float* __restrict__ x, const float* __restrict__ W,
                           const float* __restrict__ al, const float* __restrict__ ar,
                           float* __restrict__ z, float* __restrict__ el,
                           float* __restrict__ er, int n)
{
    __shared__ float xs[32][64];
    __shared__ float ws[512];
    int t = threadIdx.x;
    int base = blockIdx.x * 32;
    for (int idx = t; idx < 512; idx += 256) ws[idx] = W[idx];
    for (int idx = t; idx < 32 * 64; idx += 256) {
        int r = idx >> 6, k = idx & 63;
        int row = base + r;
        xs[r][k] = (row < n) ? x[row * 64 + k] : 0.f;
    }
    __syncthreads();
    int nl = t >> 3, j = t & 7;
    int row = base + nl;
    float acc = 0.f;
    #pragma unroll
    for (int k = 0; k < 64; k++) acc += xs[nl][k] * ws[k * 8 + j];
    float p = acc * al[j], q = acc * ar[j];
    float p2 = p + __shfl_xor_sync(0xffffffffu, p, 1);
    float q2 = q + __shfl_xor_sync(0xffffffffu, q, 1);
    if (row < n) {
        z[row * 8 + j] = acc;
        if ((j & 1) == 0) { el[row * 4 + (j >> 1)] = p2; er[row * 4 + (j >> 1)] = q2; }
    }
}

// ---------------- misc small kernels ----------------
__global__ void zero_f(float* p, int n)
{
    int i = blockIdx.x * blockDim.x + threadIdx.x;
    if (i < n) p[i] = 0.f;
}

__global__ void init_bias64(float* out, const float* __restrict__ b, int n)
{
    int i = blockIdx.x * blockDim.x + threadIdx.x;
    if (i >= n * 64) return;
    int d = i & 63;
    out[i] = b[d] + b[64 + d] + b[128 + d] + b[192 + d];
}

__global__ void init_bias2(float* out, const float* __restrict__ b, int n)
{
    int i = blockIdx.x * blockDim.x + threadIdx.x;
    if (i >= n * 2) return;
    int c = i & 1;
    out[i] = b[c] + b[2 + c] + b[4 + c] + b[6 + c];
}

// ---------------- edge pass A: exp(leaky(el+er)) + denominator ----------------
__global__ void edge_attn(const float* __restrict__ el, const float* __restrict__ er,
                          float* __restrict__ a, float* __restrict__ s,
                          const int* __restrict__ src, const int* __restrict__ dst,
                          int E, int ET)
{
    int i = blockIdx.x * blockDim.x + threadIdx.x;
    if (i >= ET) return;
    int ss, dd;
    if (i < E) { ss = src[i]; dd = dst[i]; } else { ss = dd = i - E; }
    float4 l = ((const float4*)el)[ss];
    float4 r = ((const float4*)er)[dd];
    float e0 = l.x + r.x, e1 = l.y + r.y, e2 = l.z + r.z, e3 = l.w + r.w;
    e0 = e0 > 0.f ? e0 : 0.2f * e0;
    e1 = e1 > 0.f ? e1 : 0.2f * e1;
    e2 = e2 > 0.f ? e2 : 0.2f * e2;
    e3 = e3 > 0.f ? e3 : 0.2f * e3;
    float a0 = expf(e0), a1 = expf(e1), a2 = expf(e2), a3 = expf(e3);
    ((float4*)a)[i] = make_float4(a0, a1, a2, a3);
    atomicAdd(&s[dd * 4 + 0], a0);
    atomicAdd(&s[dd * 4 + 1], a1);
    atomicAdd(&s[dd * 4 + 2], a2);
    atomicAdd(&s[dd * 4 + 3], a3);
}

// ---------------- edge pass B (D=64): warp/edge, head-summed scatter ----------------
__global__ void edge_agg64(const float* __restrict__ a, const float* __restrict__ s,
                           const float* __restrict__ z, float* __restrict__ out,
                           const int* __restrict__ src, const int* __restrict__ dst,
                           int E, int ET)
{
    int w = (blockIdx.x * blockDim.x + threadIdx.x) >> 5;
    int lane = threadIdx.x & 31;
    if (w >= ET) return;
    int ss, dd;
    if (w < E) { ss = src[w]; dd = dst[w]; } else { ss = dd = w - E; }
    float4 av = ((const float4*)a)[w];
    float4 sv = ((const float4*)s)[dd];
    float al0 = av.x / sv.x, al1 = av.y / sv.y, al2 = av.z / sv.z, al3 = av.w / sv.w;
    const float* zr = z + (size_t)ss * 256;
    float acc0 = al0 * zr[lane]      + al1 * zr[64 + lane]
               + al2 * zr[128 + lane] + al3 * zr[192 + lane];
    float acc1 = al0 * zr[32 + lane]  + al1 * zr[96 + lane]
               + al2 * zr[160 + lane] + al3 * zr[224 + lane];
    atomicAdd(&out[(size_t)dd * 64 + lane], acc0);
    atomicAdd(&out[(size_t)dd * 64 + lane + 32], acc1);
}

// ---------------- edge pass B (C=2, layer 3) ----------------
__global__ void edge_agg2(const float* __restrict__ a, const float* __restrict__ s,
                          const float* __restrict__ z, float* __restrict__ out,
                          const int* __restrict__ src, const int* __restrict__ dst,
                          int E, int ET)
{
    int i = blockIdx.x * blockDim.x + threadIdx.x;
    if (i >= ET) return;
    int ss, dd;
    if (i < E) { ss = src[i]; dd = dst[i]; } else { ss = dd = i - E; }
    float4 av = ((const float4*)a)[i];
    float4 sv = ((const float4*)s)[dd];
    float al0 = av.x / sv.x, al1 = av.y / sv.y, al2 = av.z / sv.z, al3 = av.w / sv.w;
    float4 za = ((const float4*)z)[(size_t)ss * 2];      // h0c0 h0c1 h1c0 h1c1
    float4 zb = ((const float4*)z)[(size_t)ss * 2 + 1];  // h2c0 h2c1 h3c0 h3c1
    float o0 = al0 * za.x + al1 * za.z + al2 * zb.x + al3 * zb.z;
    float o1 = al0 * za.y + al1 * za.w + al2 * zb.y + al3 * zb.w;
    atomicAdd(&out[dd * 2 + 0], o0);
    atomicAdd(&out[dd * 2 + 1], o1);
}

// ---------------- batchnorm ----------------
__global__ void bn_zero()
{
    int t = threadIdx.x;
    if (t < 64) { g_bnsum[t] = 0.0; g_bnsq[t] = 0.0; }
}

__global__ void bn_stats(const float* __restrict__ h, int n)
{
    int t = threadIdx.x;
    int d = t & 63, rsub = t >> 6;
    float sum = 0.f, sq = 0.f;
    for (int row = blockIdx.x * 4 + rsub; row < n; row += gridDim.x * 4) {
        float v = h[(size_t)row * 64 + d];
        sum += v; sq += v * v;
    }
    __shared__ float sh[256], shq[256];
    sh[t] = sum; shq[t] = sq;
    __syncthreads();
    if (t < 64) {
        float s4 = sh[t] + sh[t + 64] + sh[t + 128] + sh[t + 192];
        float q4 = shq[t] + shq[t + 64] + shq[t + 128] + shq[t + 192];
        atomicAdd(&g_bnsum[t], (double)s4);
        atomicAdd(&g_bnsq[t], (double)q4);
    }
}

__global__ void bn_final(const float* __restrict__ gamma, const float* __restrict__ beta, int n)
{
    int t = threadIdx.x;
    if (t >= 64) return;
    double mean = g_bnsum[t] / n;
    double var  = g_bnsq[t] / n - mean * mean;
    float sc = gamma[t] * rsqrtf((float)var + 1e-5f);
    g_scale[t] = sc;
    g_shift[t] = beta[t] - (float)mean * sc;
}

__global__ void bn_apply(float* __restrict__ h, int n)
{
    int i = blockIdx.x * blockDim.x + threadIdx.x;
    if (i >= n * 64) return;
    int d = i & 63;
    h[i] = h[i] * g_scale[d] + g_shift[d];
}

// ---------------- launch ----------------
extern "C" void kernel_launch(void* const* d_in, const int* in_sizes, int n_in,
                              void* d_out, int out_size)
{
    const float* feats = (const float*)d_in[0];
    const float* W1    = (const float*)d_in[1];
    const float* al1   = (const float*)d_in[2];
    const float* ar1   = (const float*)d_in[3];
    const float* b1    = (const float*)d_in[4];
    const float* Wm    = (const float*)d_in[5];
    const float* alm   = (const float*)d_in[6];
    const float* arm   = (const float*)d_in[7];
    const float* bm    = (const float*)d_in[8];
    const float* W2    = (const float*)d_in[9];
    const float* al2   = (const float*)d_in[10];
    const float* ar2   = (const float*)d_in[11];
    const float* b2    = (const float*)d_in[12];
    const float* gamma = (const float*)d_in[13];
    const float* beta  = (const float*)d_in[14];
    const int*   src   = (const int*)d_in[15];
    const int*   dst   = (const int*)d_in[16];
    float* out = (float*)d_out;

    int n  = in_sizes[0] / 9;
    int E  = in_sizes[15];
    int ET = E + n;

    void* p;
    float *z, *el, *er, *abuf, *sbuf, *h;
    cudaGetSymbolAddress(&p, g_z);  z    = (float*)p;
    cudaGetSymbolAddress(&p, g_el); el   = (float*)p;
    cudaGetSymbolAddress(&p, g_er); er   = (float*)p;
    cudaGetSymbolAddress(&p, g_a);  abuf = (float*)p;
    cudaGetSymbolAddress(&p, g_s);  sbuf = (float*)p;
    cudaGetSymbolAddress(&p, g_h);  h    = (float*)p;

    int tb = 256;
    int eblk  = (ET + tb - 1) / tb;       // thread/edge kernels
    int wblk  = (ET + 7) / 8;             // warp/edge kernels (8 warps/block)
    int nhblk = (n * 64 + tb - 1) / tb;

    // ---- Layer 1: feats[N,9] -> h[N,64] ----
    gemm256_attn<9><<<(n + 7) / 8, tb>>>(feats, W1, al1, ar1, z, el, er, n);
    zero_f<<<(n * 4 + tb - 1) / tb, tb>>>(sbuf, n * 4);
    edge_attn<<<eblk, tb>>>(el, er, abuf, sbuf, src, dst, E, ET);
    init_bias64<<<nhblk, tb>>>(h, b1, n);
    edge_agg64<<<wblk, tb>>>(abuf, sbuf, z, h, src, dst, E, ET);
    bn_zero<<<1, 64>>>();
    bn_stats<<<128, tb>>>(h, n);
    bn_final<<<1, 64>>>(gamma, beta, n);
    bn_apply<<<nhblk, tb>>>(h, n);

    // ---- Layer 2: h[N,64] -> h[N,64] ----
    gemm256_attn<64><<<(n + 7) / 8, tb>>>(h, Wm, alm, arm, z, el, er, n);
    zero_f<<<(n * 4 + tb - 1) / tb, tb>>>(sbuf, n * 4);
    edge_attn<<<eblk, tb>>>(el, er, abuf, sbuf, src, dst, E, ET);
    init_bias64<<<nhblk, tb>>>(h, bm, n);
    edge_agg64<<<wblk, tb>>>(abuf, sbuf, z, h, src, dst, E, ET);
    bn_zero<<<1, 64>>>();
    bn_stats<<<128, tb>>>(h, n);
    bn_final<<<1, 64>>>(gamma, beta, n);
    bn_apply<<<nhblk, tb>>>(h, n);

    // ---- Layer 3: h[N,64] -> out[N,2] ----
    gemm8_attn<<<(n + 31) / 32, tb>>>(h, W2, al2, ar2, z, el, er, n);
    zero_f<<<(n * 4 + tb - 1) / tb, tb>>>(sbuf, n * 4);
    edge_attn<<<eblk, tb>>>(el, er, abuf, sbuf, src, dst, E, ET);
    init_bias2<<<(n * 2 + tb - 1) / tb, tb>>>(out, b2, n);
    edge_agg2<<<eblk, tb>>>(abuf, sbuf, z, out, src, dst, E, ET);
}

// round 6
// speedup vs baseline: 1.4150x; 1.4150x over previous
#include <cuda_runtime.h>
#include <cuda_bf16.h>

#define NN 50000
#define EE 800000

// ---------------- scratch (device globals; allocation-free) ----------------
__device__ float  g_z [NN * 256];         // z buffer [N,H,D] (layer 3 reuses as [N,8])
__device__ float  g_el[NN * 4];
__device__ float  g_er[NN * 4];
__device__ float  g_h [NN * 64];          // layer activations (pre-BN)
__device__ int    g_deg[NN];
__device__ int    g_rowptr[NN + 1];
__device__ int    g_cursor[NN];
__device__ int    g_csrc[EE];             // CSR-by-dst: src ids
__device__ double g_bnsum[64], g_bnsq[64];
__device__ float  g_scale[64], g_shift[64];

// ---------------- packed f32x2 helpers (Blackwell) ----------------
__device__ __forceinline__ unsigned long long pack2(float lo, float hi) {
    unsigned long long d;
    asm("mov.b64 %0, {%1, %2};" : "=l"(d) : "f"(lo), "f"(hi));
    return d;
}
__device__ __forceinline__ void unpack2(unsigned long long d, float& lo, float& hi) {
    asm("mov.b64 {%0, %1}, %2;" : "=f"(lo), "=f"(hi) : "l"(d));
}
__device__ __forceinline__ void ffma2(unsigned long long& d, unsigned long long a,
                                      unsigned long long b) {
    asm("fma.rn.f32x2 %0, %1, %2, %0;" : "+l"(d) : "l"(a), "l"(b));
}

// ---------------- CSR build ----------------
__global__ void zero_int(int* p, int n)
{
    int i = blockIdx.x * blockDim.x + threadIdx.x;
    if (i < n) p[i] = 0;
}

__global__ void count_deg(const int* __restrict__ dst, int* __restrict__ deg, int E)
{
    int i = blockIdx.x * blockDim.x + threadIdx.x;
    if (i < E) atomicAdd(&deg[dst[i]], 1);
}

__global__ void scan_rowptr(const int* __restrict__ deg, int* __restrict__ rowptr,
                            int* __restrict__ cursor, int n)
{
    __shared__ int ts[1024];
    int t = threadIdx.x;
    int ch = (n + 1023) >> 10;
    int beg = t * ch;
    int end = beg + ch < n ? beg + ch : n;
    int s = 0;
    for (int i = beg; i < end; i++) s += deg[i];
    ts[t] = s;
    __syncthreads();
    for (int off = 1; off < 1024; off <<= 1) {
        int v = (t >= off) ? ts[t - off] : 0;
        __syncthreads();
        ts[t] += v;
        __syncthreads();
    }
    int run = ts[t] - s;   // exclusive prefix
    for (int i = beg; i < end; i++) {
        rowptr[i] = run; cursor[i] = run; run += deg[i];
    }
    if (t == 1023) rowptr[n] = ts[1023];
}

__global__ void scatter_csr(const int* __restrict__ src, const int* __restrict__ dst,
                            int* __restrict__ cursor, int* __restrict__ csrc, int E)
{
    int i = blockIdx.x * blockDim.x + threadIdx.x;
    if (i >= E) return;
    int pos = atomicAdd(&cursor[dst[i]], 1);
    csrc[pos] = src[i];
}

// ---------------- GEMM (Nout=256) + fused el/er, optional fused BN on input ----------------
// block 256 threads, 32 rows/block. thread: cols 4*(t&63), rows (t>>6)*8 .. +7 (as 4 pairs)
template<int KIN, bool APPLY_BN>
__global__ void gemm_attn(const float* __restrict__ x, const float* __restrict__ W,
                          const float* __restrict__ al, const float* __restrict__ ar,
                          float* __restrict__ z, float* __restrict__ el,
                          float* __restrict__ er, int n)
{
    __shared__ __align__(16) float xs[KIN][34];   // k-major; pad 34 (even) for banks+align
    int t = threadIdx.x;
    int base = blockIdx.x * 32;
    for (int idx = t; idx < 32 * KIN; idx += 256) {
        int r = idx / KIN, k = idx - r * KIN;     // coalesced read along k
        int row = base + r;
        float v = (row < n) ? x[(size_t)row * KIN + k] : 0.f;
        if (APPLY_BN) v = v * g_scale[k] + g_shift[k];
        xs[k][r] = v;
    }
    __syncthreads();
    int c4 = t & 63, rr = t >> 6;
    const float4* W4 = (const float4*)W;
    unsigned long long acc[4][4];
    #pragma unroll
    for (int rp = 0; rp < 4; rp++)
        #pragma unroll
        for (int c = 0; c < 4; c++) acc[rp][c] = 0ull;
    for (int k = 0; k < KIN; k++) {
        float4 w = W4[k * 64 + c4];
        unsigned long long wd0 = pack2(w.x, w.x), wd1 = pack2(w.y, w.y),
                           wd2 = pack2(w.z, w.z), wd3 = pack2(w.w, w.w);
        const unsigned long long* xp = (const unsigned long long*)(&xs[k][rr * 8]);
        #pragma unroll
        for (int rp = 0; rp < 4; rp++) {
            unsigned long long xv = xp[rp];       // rows (rr*8+2rp, +1) packed
            ffma2(acc[rp][0], xv, wd0);
            ffma2(acc[rp][1], xv, wd1);
            ffma2(acc[rp][2], xv, wd2);
            ffma2(acc[rp][3], xv, wd3);
        }
    }
    float4 alv = ((const float4*)al)[c4];
    float4 arv = ((const float4*)ar)[c4];
    #pragma unroll
    for (int rp = 0; rp < 4; rp++) {
        float v0[4], v1[4];
        unpack2(acc[rp][0], v0[0], v1[0]);
        unpack2(acc[rp][1], v0[1], v1[1]);
        unpack2(acc[rp][2], v0[2], v1[2]);
        unpack2(acc[rp][3], v0[3], v1[3]);
        #pragma unroll
        for (int half = 0; half < 2; half++) {
            float* vv = half ? v1 : v0;
            int row = base + rr * 8 + rp * 2 + half;
            if (row < n)
                ((float4*)z)[(size_t)row * 64 + c4] =
                    make_float4(vv[0], vv[1], vv[2], vv[3]);
            float p = vv[0]*alv.x + vv[1]*alv.y + vv[2]*alv.z + vv[3]*alv.w;
            float q = vv[0]*arv.x + vv[1]*arv.y + vv[2]*arv.z + vv[3]*arv.w;
            #pragma unroll
            for (int off = 8; off; off >>= 1) {
                p += __shfl_xor_sync(0xffffffffu, p, off);
                q += __shfl_xor_sync(0xffffffffu, q, off);
            }
            if ((c4 & 15) == 0 && row < n) {
                el[row * 4 + (c4 >> 4)] = p;
                er[row * 4 + (c4 >> 4)] = q;
            }
        }
    }
}

// ---------------- GEMM (Nout=8, layer 3) + fused el/er + fused BN ----------------
__global__ void gemm8_attn(const float* __restrict__ x, const float* __restrict__ W,
                           const float* __restrict__ al, const float* __restrict__ ar,
                           float* __restrict__ z, float* __restrict__ el,
                           float* __restrict__ er, int n)
{
    __shared__ float xs[32][64];
    __shared__ float ws[512];
    int t = threadIdx.x;
    int base = blockIdx.x * 32;
    for (int idx = t; idx < 512; idx += 256) ws[idx] = W[idx];
    for (int idx = t; idx < 2048; idx += 256) {
        int r = idx >> 6, k = idx & 63;
        int row = base + r;
        float v = (row < n) ? x[(size_t)row * 64 + k] : 0.f;
        xs[r][k] = v * g_scale[k] + g_shift[k];
    }
    __syncthreads();
    int nl = t >> 3, j = t & 7;
    int row = base + nl;
    float acc = 0.f;
    #pragma unroll
    for (int k = 0; k < 64; k++) acc += xs[nl][k] * ws[k * 8 + j];
    float p = acc * al[j], q = acc * ar[j];
    float p2 = p + __shfl_xor_sync(0xffffffffu, p, 1);
    float q2 = q + __shfl_xor_sync(0xffffffffu, q, 1);
    if (row < n) {
        z[(size_t)row * 8 + j] = acc;
        if ((j & 1) == 0) { el[row * 4 + (j >> 1)] = p2; er[row * 4 + (j >> 1)] = q2; }
    }
}

// ---------------- fused GAT aggregate (D=64): warp per dst node, no atomics ----------------
__global__ void gat_agg64(const float* __restrict__ el, const float* __restrict__ er,
                          const float* __restrict__ z, const int* __restrict__ rowptr,
                          const int* __restrict__ csrc, const float* __restrict__ b,
                          float* __restrict__ out, int n)
{
    int w = (blockIdx.x * blockDim.x + threadIdx.x) >> 5;
    int lane = threadIdx.x & 31;
    if (w >= n) return;
    int beg = rowptr[w], end = rowptr[w + 1];
    float4 erv = ((const float4*)er)[w];
    float num[4][2] = {};
    float den[4] = {};
    int d0 = lane * 2;
    for (int c = beg; c < end; c += 32) {
        int idx = c + lane;
        float a0 = 0.f, a1 = 0.f, a2 = 0.f, a3 = 0.f;
        int ss = 0;
        if (idx < end) {
            ss = csrc[idx];
            float4 l = ((const float4*)el)[ss];
            float e0 = l.x + erv.x, e1 = l.y + erv.y;
            float e2 = l.z + erv.z, e3 = l.w + erv.w;
            e0 = e0 > 0.f ? e0 : 0.2f * e0;
            e1 = e1 > 0.f ? e1 : 0.2f * e1;
            e2 = e2 > 0.f ? e2 : 0.2f * e2;
            e3 = e3 > 0.f ? e3 : 0.2f * e3;
            a0 = __expf(e0); a1 = __expf(e1); a2 = __expf(e2); a3 = __expf(e3);
            den[0] += a0; den[1] += a1; den[2] += a2; den[3] += a3;
        }
        int m = end - c; if (m > 32) m = 32;
        for (int j = 0; j < m; j++) {
            int   sj = __shfl_sync(0xffffffffu, ss, j);
            float b0 = __shfl_sync(0xffffffffu, a0, j);
            float b1 = __shfl_sync(0xffffffffu, a1, j);
            float b2 = __shfl_sync(0xffffffffu, a2, j);
            float b3 = __shfl_sync(0xffffffffu, a3, j);
            const float2* zp = (const float2*)(z + (size_t)sj * 256 + d0);
            float2 z0 = zp[0], z1 = zp[32], z2 = zp[64], z3 = zp[96];
            num[0][0] += b0 * z0.x; num[0][1] += b0 * z0.y;
            num[1][0] += b1 * z1.x; num[1][1] += b1 * z1.y;
            num[2][0] += b2 * z2.x; num[2][1] += b2 * z2.y;
            num[3][0] += b3 * z3.x; num[3][1] += b3 * z3.y;
        }
    }
    #pragma unroll
    for (int off = 16; off; off >>= 1) {
        den[0] += __shfl_xor_sync(0xffffffffu, den[0], off);
        den[1] += __shfl_xor_sync(0xffffffffu, den[1], off);
        den[2] += __shfl_xor_sync(0xffffffffu, den[2], off);
        den[3] += __shfl_xor_sync(0xffffffffu, den[3], off);
    }
    // self-loop (computed identically on all lanes, added once after reduction)
    {
        float4 l = ((const float4*)el)[w];
        float e0 = l.x + erv.x, e1 = l.y + erv.y;
        float e2 = l.z + erv.z, e3 = l.w + erv.w;
        e0 = e0 > 0.f ? e0 : 0.2f * e0;
        e1 = e1 > 0.f ? e1 : 0.2f * e1;
        e2 = e2 > 0.f ? e2 : 0.2f * e2;
        e3 = e3 > 0.f ? e3 : 0.2f * e3;
        float s0 = __expf(e0), s1 = __expf(e1), s2 = __expf(e2), s3 = __expf(e3);
        den[0] += s0; den[1] += s1; den[2] += s2; den[3] += s3;
        const float2* zq = (const float2*)(z + (size_t)w * 256 + d0);
        float2 q0 = zq[0], q1 = zq[32], q2 = zq[64], q3 = zq[96];
        num[0][0] += s0 * q0.x; num[0][1] += s0 * q0.y;
        num[1][0] += s1 * q1.x; num[1][1] += s1 * q1.y;
        num[2][0] += s2 * q2.x; num[2][1] += s2 * q2.y;
        num[3][0] += s3 * q3.x; num[3][1] += s3 * q3.y;
    }
    float r0 = __fdividef(1.f, den[0]);
    float r1 = __fdividef(1.f, den[1]);
    float r2 = __fdividef(1.f, den[2]);
    float r3 = __fdividef(1.f, den[3]);
    float bx = b[d0] + b[64 + d0] + b[128 + d0] + b[192 + d0];
    float by = b[d0 + 1] + b[65 + d0] + b[129 + d0] + b[193 + d0];
    float2 o;
    o.x = bx + num[0][0]*r0 + num[1][0]*r1 + num[2][0]*r2 + num[3][0]*r3;
    o.y = by + num[0][1]*r0 + num[1][1]*r1 + num[2][1]*r2 + num[3][1]*r3;
    ((float2*)out)[(size_t)w * 32 + lane] = o;
}

// ---------------- fused GAT aggregate (C=2, layer 3): warp per dst node ----------------
__global__ void gat_agg2(const float* __restrict__ el, const float* __restrict__ er,
                         const float* __restrict__ z8, const int* __restrict__ rowptr,
                         const int* __restrict__ csrc, const float* __restrict__ b,
                         float* __restrict__ out, int n)
{
    int w = (blockIdx.x * blockDim.x + threadIdx.x) >> 5;
    int lane = threadIdx.x & 31;
    if (w >= n) return;
    int beg = rowptr[w], end = rowptr[w + 1];
    float4 erv = ((const float4*)er)[w];
    float num[4][2] = {};
    float den[4] = {};
    for (int idx = beg + lane; idx < end; idx += 32) {
        int ss = csrc[idx];
        float4 l = ((const float4*)el)[ss];
        float e0 = l.x + erv.x, e1 = l.y + erv.y;
        float e2 = l.z + erv.z, e3 = l.w + erv.w;
        e0 = e0 > 0.f ? e0 : 0.2f * e0;
        e1 = e1 > 0.f ? e1 : 0.2f * e1;
        e2 = e2 > 0.f ? e2 : 0.2f * e2;
        e3 = e3 > 0.f ? e3 : 0.2f * e3;
        float a0 = __expf(e0), a1 = __expf(e1), a2 = __expf(e2), a3 = __expf(e3);
        den[0] += a0; den[1] += a1; den[2] += a2; den[3] += a3;
        float4 za = ((const float4*)z8)[(size_t)ss * 2];
        float4 zb = ((const float4*)z8)[(size_t)ss * 2 + 1];
        num[0][0] += a0 * za.x; num[0][1] += a0 * za.y;
        num[1][0] += a1 * za.z; num[1][1] += a1 * za.w;
        num[2][0] += a2 * zb.x; num[2][1] += a2 * zb.y;
        num[3][0] += a3 * zb.z; num[3][1] += a3 * zb.w;
    }
    #pragma unroll
    for (int off = 16; off; off >>= 1) {
        #pragma unroll
        for (int h = 0; h < 4; h++) {
            den[h]    += __shfl_xor_sync(0xffffffffu, den[h], off);
            num[h][0] += __shfl_xor_sync(0xffffffffu, num[h][0], off);
            num[h][1] += __shfl_xor_sync(0xffffffffu, num[h][1], off);
        }
    }
    if (lane == 0) {
        float4 l = ((const float4*)el)[w];
        float e0 = l.x + erv.x, e1 = l.y + erv.y;
        float e2 = l.z + erv.z, e3 = l.w + erv.w;
        e0 = e0 > 0.f ? e0 : 0.2f * e0;
        e1 = e1 > 0.f ? e1 : 0.2f * e1;
        e2 = e2 > 0.f ? e2 : 0.2f * e2;
        e3 = e3 > 0.f ? e3 : 0.2f * e3;
        float s0 = __expf(e0), s1 = __expf(e1), s2 = __expf(e2), s3 = __expf(e3);
        den[0] += s0; den[1] += s1; den[2] += s2; den[3] += s3;
        float4 za = ((const float4*)z8)[(size_t)w * 2];
        float4 zb = ((const float4*)z8)[(size_t)w * 2 + 1];
        num[0][0] += s0 * za.x; num[0][1] += s0 * za.y;
        num[1][0] += s1 * za.z; num[1][1] += s1 * za.w;
        num[2][0] += s2 * zb.x; num[2][1] += s2 * zb.y;
        num[3][0] += s3 * zb.z; num[3][1] += s3 * zb.w;
        float o0 = b[0] + b[2] + b[4] + b[6];
        float o1 = b[1] + b[3] + b[5] + b[7];
        o0 += num[0][0]/den[0] + num[1][0]/den[1] + num[2][0]/den[2] + num[3][0]/den[3];
        o1 += num[0][1]/den[0] + num[1][1]/den[1] + num[2][1]/den[2] + num[3][1]/den[3];
        ((float2*)out)[w] = make_float2(o0, o1);
    }
}

// ---------------- batchnorm stats ----------------
__global__ void bn_zero()
{
    int t = threadIdx.x;
    if (t < 64) { g_bnsum[t] = 0.0; g_bnsq[t] = 0.0; }
}

__global__ void bn_stats(const float* __restrict__ h, int n)
{
    int t = threadIdx.x;
    int d = t & 63, rsub = t >> 6;
    float sum = 0.f, sq = 0.f;
    for (int row = blockIdx.x * 4 + rsub; row < n; row += gridDim.x * 4) {
        float v = h[(size_t)row * 64 + d];
        sum += v; sq += v * v;
    }
    __shared__ float sh[256], shq[256];
    sh[t] = sum; shq[t] = sq;
    __syncthreads();
    if (t < 64) {
        float s4 = sh[t] + sh[t + 64] + sh[t + 128] + sh[t + 192];
        float q4 = shq[t] + shq[t + 64] + shq[t + 128] + shq[t + 192];
        atomicAdd(&g_bnsum[t], (double)s4);
        atomicAdd(&g_bnsq[t], (double)q4);
    }
}

__global__ void bn_final(const float* __restrict__ gamma, const float* __restrict__ beta, int n)
{
    int t = threadIdx.x;
    if (t >= 64) return;
    double mean = g_bnsum[t] / n;
    double var  = g_bnsq[t] / n - mean * mean;
    float sc = gamma[t] * rsqrtf((float)var + 1e-5f);
    g_scale[t] = sc;
    g_shift[t] = beta[t] - (float)mean * sc;
}

// ---------------- launch ----------------
extern "C" void kernel_launch(void* const* d_in, const int* in_sizes, int n_in,
                              void* d_out, int out_size)
{
    const float* feats = (const float*)d_in[0];
    const float* W1    = (const float*)d_in[1];
    const float* al1   = (const float*)d_in[2];
    const float* ar1   = (const float*)d_in[3];
    const float* b1    = (const float*)d_in[4];
    const float* Wm    = (const float*)d_in[5];
    const float* alm   = (const float*)d_in[6];
    const float* arm   = (const float*)d_in[7];
    const float* bm    = (const float*)d_in[8];
    const float* W2    = (const float*)d_in[9];
    const float* al2   = (const float*)d_in[10];
    const float* ar2   = (const float*)d_in[11];
    const float* b2    = (const float*)d_in[12];
    const float* gamma = (const float*)d_in[13];
    const float* beta  = (const float*)d_in[14];
    const int*   src   = (const int*)d_in[15];
    const int*   dst   = (const int*)d_in[16];
    float* out = (float*)d_out;

    int n = in_sizes[0] / 9;
    int E = in_sizes[15];

    void* p;
    float *z, *el, *er, *h;
    int *deg, *rowptr, *cursor, *csrc;
    cudaGetSymbolAddress(&p, g_z);      z      = (float*)p;
    cudaGetSymbolAddress(&p, g_el);     el     = (float*)p;
    cudaGetSymbolAddress(&p, g_er);     er     = (float*)p;
    cudaGetSymbolAddress(&p, g_h);      h      = (float*)p;
    cudaGetSymbolAddress(&p, g_deg);    deg    = (int*)p;
    cudaGetSymbolAddress(&p, g_rowptr); rowptr = (int*)p;
    cudaGetSymbolAddress(&p, g_cursor); cursor = (int*)p;
    cudaGetSymbolAddress(&p, g_csrc);   csrc   = (int*)p;

    int gblk = (n + 31) / 32;   // gemm blocks (32 rows each)
    int ablk = (n + 7) / 8;     // aggregate blocks (8 warps each)

    // ---- CSR build (reused by all 3 layers) ----
    zero_int<<<(n + 255) / 256, 256>>>(deg, n);
    count_deg<<<(E + 255) / 256, 256>>>(dst, deg, E);
    scan_rowptr<<<1, 1024>>>(deg, rowptr, cursor, n);
    scatter_csr<<<(E + 255) / 256, 256>>>(src, dst, cursor, csrc, E);

    // ---- Layer 1: feats[N,9] -> h[N,64] ----
    gemm_attn<9, false><<<gblk, 256>>>(feats, W1, al1, ar1, z, el, er, n);
    gat_agg64<<<ablk, 256>>>(el, er, z, rowptr, csrc, b1, h, n);
    bn_zero<<<1, 64>>>();
    bn_stats<<<128, 256>>>(h, n);
    bn_final<<<1, 64>>>(gamma, beta, n);

    // ---- Layer 2: bn(h) -> h[N,64]  (BN folded into gemm input load) ----
    gemm_attn<64, true><<<gblk, 256>>>(h, Wm, alm, arm, z, el, er, n);
    gat_agg64<<<ablk, 256>>>(el, er, z, rowptr, csrc, bm, h, n);
    bn_zero<<<1, 64>>>();
    bn_stats<<<128, 256>>>(h, n);
    bn_final<<<1, 64>>>(gamma, beta, n);

    // ---- Layer 3: bn(h) -> out[N,2] ----
    gemm8_attn<<<gblk, 256>>>(h, W2, al2, ar2, z, el, er, n);
    gat_agg2<<<ablk, 256>>>(el, er, z, rowptr, csrc, b2, out, n);
}

// round 10
// speedup vs baseline: 1.6032x; 1.1330x over previous
#include <cuda_runtime.h>
#include <cuda_bf16.h>
#include <cuda_fp16.h>

#define NN 50000
#define EE 800000

// ---------------- scratch (device globals; allocation-free) ----------------
__device__ float  g_z [NN * 256];         // layer 1/2: fp16 z [N,H,D]; layer 3: fp32 [N,8]
__device__ float  g_el[NN * 4];
__device__ float  g_er[NN * 4];
__device__ float  g_h [NN * 64];          // layer activations (pre-BN)
__device__ int    g_deg[NN];
__device__ int    g_rowptr[NN + 1];
__device__ int    g_cursor[NN];
__device__ int    g_csrc[EE];             // CSR-by-dst: src ids
__device__ double g_bnsum[64], g_bnsq[64];
__device__ float  g_scale[64], g_shift[64];

// ---------------- packed f32x2 helpers (Blackwell) ----------------
__device__ __forceinline__ unsigned long long pack2(float lo, float hi) {
    unsigned long long d;
    asm("mov.b64 %0, {%1, %2};" : "=l"(d) : "f"(lo), "f"(hi));
    return d;
}
__device__ __forceinline__ void unpack2(unsigned long long d, float& lo, float& hi) {
    asm("mov.b64 {%0, %1}, %2;" : "=f"(lo), "=f"(hi) : "l"(d));
}
__device__ __forceinline__ void ffma2(unsigned long long& d, unsigned long long a,
                                      unsigned long long b) {
    asm("fma.rn.f32x2 %0, %1, %2, %0;" : "+l"(d) : "l"(a), "l"(b));
}

// ---------------- CSR build ----------------
__global__ void zero_int(int* p, int n)
{
    int i = blockIdx.x * blockDim.x + threadIdx.x;
    if (i < n) p[i] = 0;
}

__global__ void count_deg(const int* __restrict__ dst, int* __restrict__ deg, int E)
{
    int i0 = (blockIdx.x * blockDim.x + threadIdx.x) * 4;
    if (i0 + 3 < E) {
        int4 d4 = *(const int4*)(dst + i0);
        atomicAdd(&deg[d4.x], 1);
        atomicAdd(&deg[d4.y], 1);
        atomicAdd(&deg[d4.z], 1);
        atomicAdd(&deg[d4.w], 1);
    } else {
        for (int i = i0; i < E; i++) atomicAdd(&deg[dst[i]], 1);
    }
}

__global__ void scan_rowptr(const int* __restrict__ deg, int* __restrict__ rowptr,
                            int* __restrict__ cursor, int n)
{
    __shared__ int ts[1024];
    int t = threadIdx.x;
    int ch = (n + 1023) >> 10;
    int beg = t * ch;
    int end = beg + ch < n ? beg + ch : n;
    int s = 0;
    for (int i = beg; i < end; i++) s += deg[i];
    ts[t] = s;
    __syncthreads();
    for (int off = 1; off < 1024; off <<= 1) {
        int v = (t >= off) ? ts[t - off] : 0;
        __syncthreads();
        ts[t] += v;
        __syncthreads();
    }
    int run = ts[t] - s;   // exclusive prefix
    for (int i = beg; i < end; i++) {
        rowptr[i] = run; cursor[i] = run; run += deg[i];
    }
    if (t == 1023) rowptr[n] = ts[1023];
}

__global__ void scatter_csr(const int* __restrict__ src, const int* __restrict__ dst,
                            int* __restrict__ cursor, int* __restrict__ csrc, int E)
{
    int i0 = (blockIdx.x * blockDim.x + threadIdx.x) * 4;
    if (i0 + 3 < E) {
        int4 d4 = *(const int4*)(dst + i0);
        int4 s4 = *(const int4*)(src + i0);
        int p0 = atomicAdd(&cursor[d4.x], 1);
        int p1 = atomicAdd(&cursor[d4.y], 1);
        int p2 = atomicAdd(&cursor[d4.z], 1);
        int p3 = atomicAdd(&cursor[d4.w], 1);
        csrc[p0] = s4.x; csrc[p1] = s4.y; csrc[p2] = s4.z; csrc[p3] = s4.w;
    } else {
        for (int i = i0; i < E; i++) {
            int pos = atomicAdd(&cursor[dst[i]], 1);
            csrc[pos] = src[i];
        }
    }
}

// ---------------- GEMM (Nout=256, fp16 z out) + fused el/er, optional fused BN ----------------
// block 256 threads, 32 rows/block. thread: cols 4*(t&63), rows (t>>6)*8 .. +7 (as 4 pairs)
template<int KIN, bool APPLY_BN>
__global__ void gemm_attn(const float* __restrict__ x, const float* __restrict__ W,
                          const float* __restrict__ al, const float* __restrict__ ar,
                          __half2* __restrict__ z, float* __restrict__ el,
                          float* __restrict__ er, int n)
{
    __shared__ __align__(16) float xs[KIN][34];   // k-major; pad 34 (even) for banks+align
    int t = threadIdx.x;
    int base = blockIdx.x * 32;
    for (int idx = t; idx < 32 * KIN; idx += 256) {
        int r = idx / KIN, k = idx - r * KIN;     // coalesced read along k
        int row = base + r;
        float v = (row < n) ? x[(size_t)row * KIN + k] : 0.f;
        if (APPLY_BN) v = v * g_scale[k] + g_shift[k];
        xs[k][r] = v;
    }
    __syncthreads();
    int c4 = t & 63, rr = t >> 6;
    const float4* W4 = (const float4*)W;
    unsigned long long acc[4][4];
    #pragma unroll
    for (int rp = 0; rp < 4; rp++)
        #pragma unroll
        for (int c = 0; c < 4; c++) acc[rp][c] = 0ull;
    for (int k = 0; k < KIN; k++) {
        float4 w = W4[k * 64 + c4];
        unsigned long long wd0 = pack2(w.x, w.x), wd1 = pack2(w.y, w.y),
                           wd2 = pack2(w.z, w.z), wd3 = pack2(w.w, w.w);
        const unsigned long long* xp = (const unsigned long long*)(&xs[k][rr * 8]);
        #pragma unroll
        for (int rp = 0; rp < 4; rp++) {
            unsigned long long xv = xp[rp];       // rows (rr*8+2rp, +1) packed
            ffma2(acc[rp][0], xv, wd0);
            ffma2(acc[rp][1], xv, wd1);
            ffma2(acc[rp][2], xv, wd2);
            ffma2(acc[rp][3], xv, wd3);
        }
    }
    float4 alv = ((const float4*)al)[c4];
    float4 arv = ((const float4*)ar)[c4];
    #pragma unroll
    for (int rp = 0; rp < 4; rp++) {
        float v0[4], v1[4];
        unpack2(acc[rp][0], v0[0], v1[0]);
        unpack2(acc[rp][1], v0[1], v1[1]);
        unpack2(acc[rp][2], v0[2], v1[2]);
        unpack2(acc[rp][3], v0[3], v1[3]);
        #pragma unroll
        for (int half = 0; half < 2; half++) {
            float* vv = half ? v1 : v0;
            int row = base + rr * 8 + rp * 2 + half;
            if (row < n) {
                __half2 ha = __floats2half2_rn(vv[0], vv[1]);
                __half2 hb = __floats2half2_rn(vv[2], vv[3]);
                __half2* zp = z + (size_t)row * 128 + c4 * 2;
                zp[0] = ha; zp[1] = hb;
            }
            float p = vv[0]*alv.x + vv[1]*alv.y + vv[2]*alv.z + vv[3]*alv.w;
            float q = vv[0]*arv.x + vv[1]*arv.y + vv[2]*arv.z + vv[3]*arv.w;
            #pragma unroll
            for (int off = 8; off; off >>= 1) {
                p += __shfl_xor_sync(0xffffffffu, p, off);
                q += __shfl_xor_sync(0xffffffffu, q, off);
            }
            if ((c4 & 15) == 0 && row < n) {
                el[row * 4 + (c4 >> 4)] = p;
                er[row * 4 + (c4 >> 4)] = q;
            }
        }
    }
}

// ---------------- GEMM (Nout=8, layer 3, fp32 z) + fused el/er + fused BN ----------------
__global__ void gemm8_attn(const float* __restrict__ x, const float* __restrict__ W,
                           const float* __restrict__ al, const float* __restrict__ ar,
                           float* __restrict__ z, float* __restrict__ el,
                           float* __restrict__ er, int n)
{
    __shared__ float xs[32][64];
    __shared__ float ws[512];
    int t = threadIdx.x;
    int base = blockIdx.x * 32;
    for (int idx = t; idx < 512; idx += 256) ws[idx] = W[idx];
    for (int idx = t; idx < 2048; idx += 256) {
        int r = idx >> 6, k = idx & 63;
        int row = base + r;
        float v = (row < n) ? x[(size_t)row * 64 + k] : 0.f;
        xs[r][k] = v * g_scale[k] + g_shift[k];
    }
    __syncthreads();
    int nl = t >> 3, j = t & 7;
    int row = base + nl;
    float acc = 0.f;
    #pragma unroll
    for (int k = 0; k < 64; k++) acc += xs[nl][k] * ws[k * 8 + j];
    float p = acc * al[j], q = acc * ar[j];
    float p2 = p + __shfl_xor_sync(0xffffffffu, p, 1);
    float q2 = q + __shfl_xor_sync(0xffffffffu, q, 1);
    if (row < n) {
        z[(size_t)row * 8 + j] = acc;
        if ((j & 1) == 0) { el[row * 4 + (j >> 1)] = p2; er[row * 4 + (j >> 1)] = q2; }
    }
}

// ---------------- fused GAT aggregate (D=64, fp16 z): warp per dst node ----------------
__global__ void gat_agg64(const float* __restrict__ el, const float* __restrict__ er,
                          const __half2* __restrict__ z, const int* __restrict__ rowptr,
                          const int* __restrict__ csrc, const float* __restrict__ b,
                          float* __restrict__ out, int n)
{
    int w = (blockIdx.x * blockDim.x + threadIdx.x) >> 5;
    int lane = threadIdx.x & 31;
    if (w >= n) return;
    int beg = rowptr[w], end = rowptr[w + 1];
    float4 erv = ((const float4*)er)[w];
    float num[4][2] = {};
    float den[4] = {};
    int d0 = lane * 2;
    for (int c = beg; c < end; c += 32) {
        int idx = c + lane;
        float a0 = 0.f, a1 = 0.f, a2 = 0.f, a3 = 0.f;
        int ss = 0;
        if (idx < end) {
            ss = csrc[idx];
            float4 l = ((const float4*)el)[ss];
            float e0 = l.x + erv.x, e1 = l.y + erv.y;
            float e2 = l.z + erv.z, e3 = l.w + erv.w;
            e0 = e0 > 0.f ? e0 : 0.2f * e0;
            e1 = e1 > 0.f ? e1 : 0.2f * e1;
            e2 = e2 > 0.f ? e2 : 0.2f * e2;
            e3 = e3 > 0.f ? e3 : 0.2f * e3;
            a0 = __expf(e0); a1 = __expf(e1); a2 = __expf(e2); a3 = __expf(e3);
            den[0] += a0; den[1] += a1; den[2] += a2; den[3] += a3;
        }
        int m = end - c; if (m > 32) m = 32;
        for (int j = 0; j < m; j++) {
            int   sj = __shfl_sync(0xffffffffu, ss, j);
            float b0 = __shfl_sync(0xffffffffu, a0, j);
            float b1 = __shfl_sync(0xffffffffu, a1, j);
            float b2 = __shfl_sync(0xffffffffu, a2, j);
            float b3 = __shfl_sync(0xffffffffu, a3, j);
            const __half2* zp = z + (size_t)sj * 128 + lane;
            float2 z0 = __half22float2(zp[0]);
            float2 z1 = __half22float2(zp[32]);
            float2 z2 = __half22float2(zp[64]);
            float2 z3 = __half22float2(zp[96]);
            num[0][0] += b0 * z0.x; num[0][1] += b0 * z0.y;
            num[1][0] += b1 * z1.x; num[1][1] += b1 * z1.y;
            num[2][0] += b2 * z2.x; num[2][1] += b2 * z2.y;
            num[3][0] += b3 * z3.x; num[3][1] += b3 * z3.y;
        }
    }
    #pragma unroll
    for (int off = 16; off; off >>= 1) {
        den[0] += __shfl_xor_sync(0xffffffffu, den[0], off);
        den[1] += __shfl_xor_sync(0xffffffffu, den[1], off);
        den[2] += __shfl_xor_sync(0xffffffffu, den[2], off);
        den[3] += __shfl_xor_sync(0xffffffffu, den[3], off);
    }
    // self-loop (computed identically on all lanes, added once after reduction)
    {
        float4 l = ((const float4*)el)[w];
        float e0 = l.x + erv.x, e1 = l.y + erv.y;
        float e2 = l.z + erv.z, e3 = l.w + erv.w;
        e0 = e0 > 0.f ? e0 : 0.2f * e0;
        e1 = e1 > 0.f ? e1 : 0.2f * e1;
        e2 = e2 > 0.f ? e2 : 0.2f * e2;
        e3 = e3 > 0.f ? e3 : 0.2f * e3;
        float s0 = __expf(e0), s1 = __expf(e1), s2 = __expf(e2), s3 = __expf(e3);
        den[0] += s0; den[1] += s1; den[2] += s2; den[3] += s3;
        const __half2* zq = z + (size_t)w * 128 + lane;
        float2 q0 = __half22float2(zq[0]);
        float2 q1 = __half22float2(zq[32]);
        float2 q2 = __half22float2(zq[64]);
        float2 q3 = __half22float2(zq[96]);
        num[0][0] += s0 * q0.x; num[0][1] += s0 * q0.y;
        num[1][0] += s1 * q1.x; num[1][1] += s1 * q1.y;
        num[2][0] += s2 * q2.x; num[2][1] += s2 * q2.y;
        num[3][0] += s3 * q3.x; num[3][1] += s3 * q3.y;
    }
    float r0 = __fdividef(1.f, den[0]);
    float r1 = __fdividef(1.f, den[1]);
    float r2 = __fdividef(1.f, den[2]);
    float r3 = __fdividef(1.f, den[3]);
    float bx = b[d0] + b[64 + d0] + b[128 + d0] + b[192 + d0];
    float by = b[d0 + 1] + b[65 + d0] + b[129 + d0] + b[193 + d0];
    float2 o;
    o.x = bx + num[0][0]*r0 + num[1][0]*r1 + num[2][0]*r2 + num[3][0]*r3;
    o.y = by + num[0][1]*r0 + num[1][1]*r1 + num[2][1]*r2 + num[3][1]*r3;
    ((float2*)out)[(size_t)w * 32 + lane] = o;
}

// ---------------- fused GAT aggregate (C=2, layer 3, fp32 z): warp per dst node ----------------
__global__ void gat_agg2(const float* __restrict__ el, const float* __restrict__ er,
                         const float* __restrict__ z8, const int* __restrict__ rowptr,
                         const int* __restrict__ csrc, const float* __restrict__ b,
                         float* __restrict__ out, int n)
{
    int w = (blockIdx.x * blockDim.x + threadIdx.x) >> 5;
    int lane = threadIdx.x & 31;
    if (w >= n) return;
    int beg = rowptr[w], end = rowptr[w + 1];
    float4 erv = ((const float4*)er)[w];
    float num[4][2] = {};
    float den[4] = {};
    for (int idx = beg + lane; idx < end; idx += 32) {
        int ss = csrc[idx];
        float4 l = ((const float4*)el)[ss];
        float e0 = l.x + erv.x, e1 = l.y + erv.y;
        float e2 = l.z + erv.z, e3 = l.w + erv.w;
        e0 = e0 > 0.f ? e0 : 0.2f * e0;
        e1 = e1 > 0.f ? e1 : 0.2f * e1;
        e2 = e2 > 0.f ? e2 : 0.2f * e2;
        e3 = e3 > 0.f ? e3 : 0.2f * e3;
        float a0 = __expf(e0), a1 = __expf(e1), a2 = __expf(e2), a3 = __expf(e3);
        den[0] += a0; den[1] += a1; den[2] += a2; den[3] += a3;
        float4 za = ((const float4*)z8)[(size_t)ss * 2];
        float4 zb = ((const float4*)z8)[(size_t)ss * 2 + 1];
        num[0][0] += a0 * za.x; num[0][1] += a0 * za.y;
        num[1][0] += a1 * za.z; num[1][1] += a1 * za.w;
        num[2][0] += a2 * zb.x; num[2][1] += a2 * zb.y;
        num[3][0] += a3 * zb.z; num[3][1] += a3 * zb.w;
    }
    #pragma unroll
    for (int off = 16; off; off >>= 1) {
        #pragma unroll
        for (int h = 0; h < 4; h++) {
            den[h]    += __shfl_xor_sync(0xffffffffu, den[h], off);
            num[h][0] += __shfl_xor_sync(0xffffffffu, num[h][0], off);
            num[h][1] += __shfl_xor_sync(0xffffffffu, num[h][1], off);
        }
    }
    if (lane == 0) {
        float4 l = ((const float4*)el)[w];
        float e0 = l.x + erv.x, e1 = l.y + erv.y;
        float e2 = l.z + erv.z, e3 = l.w + erv.w;
        e0 = e0 > 0.f ? e0 : 0.2f * e0;
        e1 = e1 > 0.f ? e1 : 0.2f * e1;
        e2 = e2 > 0.f ? e2 : 0.2f * e2;
        e3 = e3 > 0.f ? e3 : 0.2f * e3;
        float s0 = __expf(e0), s1 = __expf(e1), s2 = __expf(e2), s3 = __expf(e3);
        den[0] += s0; den[1] += s1; den[2] += s2; den[3] += s3;
        float4 za = ((const float4*)z8)[(size_t)w * 2];
        float4 zb = ((const float4*)z8)[(size_t)w * 2 + 1];
        num[0][0] += s0 * za.x; num[0][1] += s0 * za.y;
        num[1][0] += s1 * za.z; num[1][1] += s1 * za.w;
        num[2][0] += s2 * zb.x; num[2][1] += s2 * zb.y;
        num[3][0] += s3 * zb.z; num[3][1] += s3 * zb.w;
        float o0 = b[0] + b[2] + b[4] + b[6];
        float o1 = b[1] + b[3] + b[5] + b[7];
        o0 += num[0][0]/den[0] + num[1][0]/den[1] + num[2][0]/den[2] + num[3][0]/den[3];
        o1 += num[0][1]/den[0] + num[1][1]/den[1] + num[2][1]/den[2] + num[3][1]/den[3];
        ((float2*)out)[w] = make_float2(o0, o1);
    }
}

// ---------------- batchnorm stats ----------------
__global__ void bn_zero()
{
    int t = threadIdx.x;
    if (t < 64) { g_bnsum[t] = 0.0; g_bnsq[t] = 0.0; }
}

__global__ void bn_stats(const float* __restrict__ h, int n)
{
    int t = threadIdx.x;
    int d = t & 63, rsub = t >> 6;
    float sum = 0.f, sq = 0.f;
    for (int row = blockIdx.x * 4 + rsub; row < n; row += gridDim.x * 4) {
        float v = h[(size_t)row * 64 + d];
        sum += v; sq += v * v;
    }
    __shared__ float sh[256], shq[256];
    sh[t] = sum; shq[t] = sq;
    __syncthreads();
    if (t < 64) {
        float s4 = sh[t] + sh[t + 64] + sh[t + 128] + sh[t + 192];
        float q4 = shq[t] + shq[t + 64] + shq[t + 128] + shq[t + 192];
        atomicAdd(&g_bnsum[t], (double)s4);
        atomicAdd(&g_bnsq[t], (double)q4);
    }
}

__global__ void bn_final(const float* __restrict__ gamma, const float* __restrict__ beta, int n)
{
    int t = threadIdx.x;
    if (t >= 64) return;
    double mean = g_bnsum[t] / n;
    double var  = g_bnsq[t] / n - mean * mean;
    float sc = gamma[t] * rsqrtf((float)var + 1e-5f);
    g_scale[t] = sc;
    g_shift[t] = beta[t] - (float)mean * sc;
}

// ---------------- launch ----------------
extern "C" void kernel_launch(void* const* d_in, const int* in_sizes, int n_in,
                              void* d_out, int out_size)
{
    const float* feats = (const float*)d_in[0];
    const float* W1    = (const float*)d_in[1];
    const float* al1   = (const float*)d_in[2];
    const float* ar1   = (const float*)d_in[3];
    const float* b1    = (const float*)d_in[4];
    const float* Wm    = (const float*)d_in[5];
    const float* alm   = (const float*)d_in[6];
    const float* arm   = (const float*)d_in[7];
    const float* bm    = (const float*)d_in[8];
    const float* W2    = (const float*)d_in[9];
    const float* al2   = (const float*)d_in[10];
    const float* ar2   = (const float*)d_in[11];
    const float* b2    = (const float*)d_in[12];
    const float* gamma = (const float*)d_in[13];
    const float* beta  = (const float*)d_in[14];
    const int*   src   = (const int*)d_in[15];
    const int*   dst   = (const int*)d_in[16];
    float* out = (float*)d_out;

    int n = in_sizes[0] / 9;
    int E = in_sizes[15];

    void* p;
    float *z, *el, *er, *h;
    int *deg, *rowptr, *cursor, *csrc;
    cudaGetSymbolAddress(&p, g_z);      z      = (float*)p;
    cudaGetSymbolAddress(&p, g_el);     el     = (float*)p;
    cudaGetSymbolAddress(&p, g_er);     er     = (float*)p;
    cudaGetSymbolAddress(&p, g_h);      h      = (float*)p;
    cudaGetSymbolAddress(&p, g_deg);    deg    = (int*)p;
    cudaGetSymbolAddress(&p, g_rowptr); rowptr = (int*)p;
    cudaGetSymbolAddress(&p, g_cursor); cursor = (int*)p;
    cudaGetSymbolAddress(&p, g_csrc);   csrc   = (int*)p;
    __half2* zh = (__half2*)z;

    int gblk = (n + 31) / 32;   // gemm blocks (32 rows each)
    int ablk = (n + 7) / 8;     // aggregate blocks (8 warps each)
    int e4blk = (E / 4 + 256) / 256;

    // ---- CSR build (reused by all 3 layers) ----
    zero_int<<<(n + 255) / 256, 256>>>(deg, n);
    count_deg<<<e4blk, 256>>>(dst, deg, E);
    scan_rowptr<<<1, 1024>>>(deg, rowptr, cursor, n);
    scatter_csr<<<e4blk, 256>>>(src, dst, cursor, csrc, E);

    // ---- Layer 1: feats[N,9] -> h[N,64] ----
    gemm_attn<9, false><<<gblk, 256>>>(feats, W1, al1, ar1, zh, el, er, n);
    gat_agg64<<<ablk, 256>>>(el, er, zh, rowptr, csrc, b1, h, n);
    bn_zero<<<1, 64>>>();
    bn_stats<<<128, 256>>>(h, n);
    bn_final<<<1, 64>>>(gamma, beta, n);

    // ---- Layer 2: bn(h) -> h[N,64]  (BN folded into gemm input load) ----
    gemm_attn<64, true><<<gblk, 256>>>(h, Wm, alm, arm, zh, el, er, n);
    gat_agg64<<<ablk, 256>>>(el, er, zh, rowptr, csrc, bm, h, n);
    bn_zero<<<1, 64>>>();
    bn_stats<<<128, 256>>>(h, n);
    bn_final<<<1, 64>>>(gamma, beta, n);

    // ---- Layer 3: bn(h) -> out[N,2] ----
    gemm8_attn<<<gblk, 256>>>(h, W2, al2, ar2, z, el, er, n);
    gat_agg2<<<ablk, 256>>>(el, er, z, rowptr, csrc, b2, out, n);
}